// round 3
// baseline (speedup 1.0000x reference)
#include <cuda_runtime.h>

#define B     64
#define T     512
#define DIN   256
#define H     1024
#define DOUT  256
#define NCTA  128
#define NT    256

// Persistent state (device globals — no allocations allowed)
__device__ float g_h0[2][B * H];
__device__ float g_h1[2][B * H];
__device__ unsigned g_bar_count;   // monotonic grid-barrier counter
__device__ unsigned g_done;        // end-of-kernel reset rendezvous

// Packed fp32x2 FMA: 2 exact fp32 MACs per instruction.
__device__ __forceinline__ void fma2(float2& c, float2 a, float2 b) {
    unsigned long long& cc = reinterpret_cast<unsigned long long&>(c);
    unsigned long long aa = reinterpret_cast<unsigned long long&>(a);
    unsigned long long bb = reinterpret_cast<unsigned long long&>(b);
    asm("fma.rn.f32x2 %0, %1, %2, %0;" : "+l"(cc) : "l"(aa), "l"(bb));
}

__device__ __forceinline__ float sigf(float x) {
    return __fdividef(1.0f, 1.0f + __expf(-x));
}
__device__ __forceinline__ float tanh_(float x) {
    return __fdividef(2.0f, 1.0f + __expf(-2.0f * x)) - 1.0f;
}

// Grid-wide barrier: release-fence + arrive; spin (thread 0) until target; acquire-fence.
// gpu-scope fence emits CCTL.IVALL -> whole SM's L1D invalidated -> fresh h reads.
__device__ __forceinline__ void grid_sync(unsigned target) {
    __syncthreads();
    if (threadIdx.x == 0) {
        __threadfence();
        atomicAdd(&g_bar_count, 1u);
        while (*((volatile unsigned*)&g_bar_count) < target) { }
        __threadfence();
    }
    __syncthreads();
}

// Warp reduction over the 8 k-slices (lanes l, l+4, ..., l+28). Valid on lanes 0..3.
__device__ __forceinline__ float redk(float2 v) {
    float x = v.x + v.y;
    x += __shfl_down_sync(0xffffffffu, x, 16);
    x += __shfl_down_sync(0xffffffffu, x, 8);
    x += __shfl_down_sync(0xffffffffu, x, 4);
    return x;
}

// One GEMM phase: accumulate A[b,:] . W[gate*H + j, :] over K into (ar, az, an).
// Thread covers j0, j0+1 (jv=2), b0..b0+7 (bv=8), k in {4s+32m + 128*k0blk}.
// Warp lanes: jgrp = lane&3 (broadcast on act loads), s = lane>>2 (one 128B line
// per weight row per LDG across the 8 slices).
template<int K, int ASTR>
__device__ __forceinline__ void gemm_phase(
    const float* __restrict__ A, const float* __restrict__ W,
    int j0, int s, int b0,
    float2 (&ar)[2][8], float2 (&az)[2][8], float2 (&an)[2][8])
{
    const float* ap[8];
#pragma unroll
    for (int bb = 0; bb < 8; bb++)
        ap[bb] = A + (size_t)(b0 + bb) * ASTR + 4 * s;
    const float* wp[6];
#pragma unroll
    for (int g = 0; g < 3; g++)
#pragma unroll
        for (int jj = 0; jj < 2; jj++)
            wp[g * 2 + jj] = W + ((size_t)g * H + j0 + jj) * K + 4 * s;

#pragma unroll 1
    for (int k0 = 0; k0 < K; k0 += 128) {
#pragma unroll
        for (int m = 0; m < 4; m++) {
            const int off = 32 * m;
            float4 wv[6];
#pragma unroll
            for (int i = 0; i < 6; i++)
                wv[i] = *reinterpret_cast<const float4*>(wp[i] + off);
#pragma unroll
            for (int bb = 0; bb < 8; bb++) {
                float4 a4 = *reinterpret_cast<const float4*>(ap[bb] + off);
                float2 alo = make_float2(a4.x, a4.y);
                float2 ahi = make_float2(a4.z, a4.w);
#pragma unroll
                for (int jj = 0; jj < 2; jj++) {
                    fma2(ar[jj][bb], alo, make_float2(wv[0 + jj].x, wv[0 + jj].y));
                    fma2(ar[jj][bb], ahi, make_float2(wv[0 + jj].z, wv[0 + jj].w));
                    fma2(az[jj][bb], alo, make_float2(wv[2 + jj].x, wv[2 + jj].y));
                    fma2(az[jj][bb], ahi, make_float2(wv[2 + jj].z, wv[2 + jj].w));
                    fma2(an[jj][bb], alo, make_float2(wv[4 + jj].x, wv[4 + jj].y));
                    fma2(an[jj][bb], ahi, make_float2(wv[4 + jj].z, wv[4 + jj].w));
                }
            }
        }
#pragma unroll
        for (int bb = 0; bb < 8; bb++) ap[bb] += 128;
#pragma unroll
        for (int i = 0; i < 6; i++) wp[i] += 128;
    }
}

// GRU gate epilogue: reduce k-slices, apply gates, write h'.
__device__ __forceinline__ void gru_epilogue(
    float2 (&ar)[2][8], float2 (&az)[2][8],
    float2 (&ain)[2][8], float2 (&ahn)[2][8],
    const float (&bs)[2][4],
    const float* __restrict__ hprev, float* __restrict__ hout,
    int j0, int b0, int lane)
{
#pragma unroll
    for (int jj = 0; jj < 2; jj++) {
#pragma unroll
        for (int bb = 0; bb < 8; bb++) {
            float rr = redk(ar[jj][bb]);
            float zz = redk(az[jj][bb]);
            float ii = redk(ain[jj][bb]);
            float hh = redk(ahn[jj][bb]);
            if (lane < 4) {
                int j = j0 + jj;
                int b = b0 + bb;
                float r = sigf(rr + bs[jj][0]);
                float z = sigf(zz + bs[jj][1]);
                float n = tanh_(ii + bs[jj][2] + r * (hh + bs[jj][3]));
                float hp = hprev[(size_t)b * H + j];
                hout[(size_t)b * H + j] = n + z * (hp - n);
            }
        }
    }
}

__global__ void __launch_bounds__(NT, 1) gru_persistent(
    const float* __restrict__ x,
    const float* __restrict__ Wi0, const float* __restrict__ Wh0,
    const float* __restrict__ bi0, const float* __restrict__ bh0,
    const float* __restrict__ Wi1, const float* __restrict__ Wh1,
    const float* __restrict__ bi1, const float* __restrict__ bh1,
    const float* __restrict__ Wo,  const float* __restrict__ bo,
    float* __restrict__ out)
{
    const int tid   = threadIdx.x;
    const int lane  = tid & 31;
    const int warp  = tid >> 5;
    const int jgrp  = lane & 3;
    const int s     = lane >> 2;
    const int b0    = warp * 8;
    const int jbase = blockIdx.x * 8;
    const int j0    = jbase + jgrp * 2;

    // Zero initial state buffers (buffer 0 only; buffer 1 is written before read)
    for (int i = blockIdx.x * NT + tid; i < B * H; i += NCTA * NT) {
        g_h0[0][i] = 0.0f;
        g_h1[0][i] = 0.0f;
    }

    // Preload bias sums for this thread's two j's, both layers
    float bs0[2][4], bs1[2][4];
#pragma unroll
    for (int jj = 0; jj < 2; jj++) {
        int j = j0 + jj;
        bs0[jj][0] = bi0[j] + bh0[j];
        bs0[jj][1] = bi0[H + j] + bh0[H + j];
        bs0[jj][2] = bi0[2 * H + j];
        bs0[jj][3] = bh0[2 * H + j];
        bs1[jj][0] = bi1[j] + bh1[j];
        bs1[jj][1] = bi1[H + j] + bh1[H + j];
        bs1[jj][2] = bi1[2 * H + j];
        bs1[jj][3] = bh1[2 * H + j];
    }

    unsigned gen = 0;
    grid_sync(++gen * NCTA);   // h init visible everywhere

    for (int t = 0; t < T; t++) {
        const int pp = t & 1, cc = pp ^ 1;
        const float* h0p = g_h0[pp];
        float*       h0n = g_h0[cc];
        const float* h1p = g_h1[pp];
        float*       h1n = g_h1[cc];

        float2 ar[2][8], az[2][8], ain[2][8], ahn[2][8];
#pragma unroll
        for (int jj = 0; jj < 2; jj++)
#pragma unroll
            for (int bb = 0; bb < 8; bb++) {
                ar[jj][bb] = make_float2(0.f, 0.f);
                az[jj][bb] = make_float2(0.f, 0.f);
                ain[jj][bb] = make_float2(0.f, 0.f);
                ahn[jj][bb] = make_float2(0.f, 0.f);
            }

        // Layer 0: gi = x_t @ Wi0^T ; gh = h0 @ Wh0^T
        gemm_phase<DIN, T * DIN>(x + (size_t)t * DIN, Wi0, j0, s, b0, ar, az, ain);
        gemm_phase<H, H>(h0p, Wh0, j0, s, b0, ar, az, ahn);
        gru_epilogue(ar, az, ain, ahn, bs0, h0p, h0n, j0, b0, lane);

        grid_sync(++gen * NCTA);   // h0' visible

        // Layer 1: gi = h0' @ Wi1^T ; gh = h1 @ Wh1^T
#pragma unroll
        for (int jj = 0; jj < 2; jj++)
#pragma unroll
            for (int bb = 0; bb < 8; bb++) {
                ar[jj][bb] = make_float2(0.f, 0.f);
                az[jj][bb] = make_float2(0.f, 0.f);
                ain[jj][bb] = make_float2(0.f, 0.f);
                ahn[jj][bb] = make_float2(0.f, 0.f);
            }
        gemm_phase<H, H>(h0n, Wi1, j0, s, b0, ar, az, ain);
        gemm_phase<H, H>(h1p, Wh1, j0, s, b0, ar, az, ahn);
        gru_epilogue(ar, az, ain, ahn, bs1, h1p, h1n, j0, b0, lane);

        grid_sync(++gen * NCTA);   // h1' visible
    }

    // Output projection: out[b, o] = h1_final[b,:] . Wo[o,:] + bo[o]
    // h1 final lives in g_h1[0] (t=511 wrote buffer 0). CTA handles o = 2*bid, 2*bid+1.
    {
        __shared__ float red[NT];
        const int e  = tid & 127;
        const int kh = tid >> 7;
        const int b  = e & 63;
        const int o  = blockIdx.x * 2 + (e >> 6);
        const float* w  = Wo + (size_t)o * H + kh * 512;
        const float* hh = g_h1[0] + (size_t)b * H + kh * 512;
        float2 acc = make_float2(0.f, 0.f);
#pragma unroll 8
        for (int k = 0; k < 512; k += 4) {
            float4 wv = *reinterpret_cast<const float4*>(w + k);
            float4 hv = *reinterpret_cast<const float4*>(hh + k);
            fma2(acc, make_float2(hv.x, hv.y), make_float2(wv.x, wv.y));
            fma2(acc, make_float2(hv.z, hv.w), make_float2(wv.z, wv.w));
        }
        red[tid] = acc.x + acc.y;
        __syncthreads();
        if (tid < 128) {
            out[(size_t)b * DOUT + o] = red[tid] + red[tid + 128] + bo[o];
        }
    }

    // Reset barrier counters for the next launch. The last CTA to arrive here
    // is ordered after every CTA has exited its final spin, so this is race-free.
    __syncthreads();
    if (tid == 0) {
        unsigned old = atomicAdd(&g_done, 1u);
        if (old == NCTA - 1u) {
            g_bar_count = 0u;
            g_done = 0u;
            __threadfence();
        }
    }
}

extern "C" void kernel_launch(void* const* d_in, const int* in_sizes, int n_in,
                              void* d_out, int out_size)
{
    const float* x   = (const float*)d_in[0];
    const float* Wi0 = (const float*)d_in[1];
    const float* Wh0 = (const float*)d_in[2];
    const float* bi0 = (const float*)d_in[3];
    const float* bh0 = (const float*)d_in[4];
    const float* Wi1 = (const float*)d_in[5];
    const float* Wh1 = (const float*)d_in[6];
    const float* bi1 = (const float*)d_in[7];
    const float* bh1 = (const float*)d_in[8];
    const float* Wo  = (const float*)d_in[9];
    const float* bo  = (const float*)d_in[10];
    float* out = (float*)d_out;

    gru_persistent<<<NCTA, NT>>>(x, Wi0, Wh0, bi0, bh0,
                                 Wi1, Wh1, bi1, bh1, Wo, bo, out);
}

// round 4
// speedup vs baseline: 1.0021x; 1.0021x over previous
#include <cuda_runtime.h>

#define B     64
#define T     512
#define DIN   256
#define H     1024
#define DOUT  256
#define NCTA  128
#define NT    256

// Persistent state (device globals — no allocations allowed)
__device__ float g_h0[2][B * H];
__device__ float g_h1[2][B * H];
__device__ unsigned g_bar_count;   // monotonic grid-barrier counter
__device__ unsigned g_done;        // end-of-kernel reset rendezvous

// Packed fp32x2 FMA: 2 exact fp32 MACs per instruction.
__device__ __forceinline__ void fma2(float2& c, float2 a, float2 b) {
    unsigned long long& cc = reinterpret_cast<unsigned long long&>(c);
    unsigned long long aa = reinterpret_cast<unsigned long long&>(a);
    unsigned long long bb = reinterpret_cast<unsigned long long&>(b);
    asm("fma.rn.f32x2 %0, %1, %2, %0;" : "+l"(cc) : "l"(aa), "l"(bb));
}

__device__ __forceinline__ float sigf(float x) {
    return __fdividef(1.0f, 1.0f + __expf(-x));
}
__device__ __forceinline__ float tanh_(float x) {
    return __fdividef(2.0f, 1.0f + __expf(-2.0f * x)) - 1.0f;
}

// Grid-wide barrier: release-fence + arrive; spin (thread 0) until target; acquire-fence.
// gpu-scope fence emits CCTL.IVALL -> whole SM's L1D invalidated -> fresh h reads.
__device__ __forceinline__ void grid_sync(unsigned target) {
    __syncthreads();
    if (threadIdx.x == 0) {
        __threadfence();
        atomicAdd(&g_bar_count, 1u);
        while (*((volatile unsigned*)&g_bar_count) < target) { }
        __threadfence();
    }
    __syncthreads();
}

// Warp reduction over the 8 k-slices (lanes l, l+4, ..., l+28). Valid on lanes 0..3.
__device__ __forceinline__ float redk(float2 v) {
    float x = v.x + v.y;
    x += __shfl_down_sync(0xffffffffu, x, 16);
    x += __shfl_down_sync(0xffffffffu, x, 8);
    x += __shfl_down_sync(0xffffffffu, x, 4);
    return x;
}

// One GEMM phase: accumulate A[b,:] . W[gate*H + j, :] over K into (ar, az, an).
// Thread covers j0, j0+1 (jv=2), b0..b0+7 (bv=8), k in {4s+32m + 128*k0blk}.
// Warp lanes: jgrp = lane&3 (broadcast on act loads), s = lane>>2 (one 128B line
// per weight row per LDG across the 8 slices).
template<int K, int ASTR>
__device__ __forceinline__ void gemm_phase(
    const float* __restrict__ A, const float* __restrict__ W,
    int j0, int s, int b0,
    float2 (&ar)[2][8], float2 (&az)[2][8], float2 (&an)[2][8])
{
    const float* ap[8];
#pragma unroll
    for (int bb = 0; bb < 8; bb++)
        ap[bb] = A + (size_t)(b0 + bb) * ASTR + 4 * s;
    const float* wp[6];
#pragma unroll
    for (int g = 0; g < 3; g++)
#pragma unroll
        for (int jj = 0; jj < 2; jj++)
            wp[g * 2 + jj] = W + ((size_t)g * H + j0 + jj) * K + 4 * s;

#pragma unroll 1
    for (int k0 = 0; k0 < K; k0 += 128) {
#pragma unroll
        for (int m = 0; m < 4; m++) {
            const int off = 32 * m;
            float4 wv[6];
#pragma unroll
            for (int i = 0; i < 6; i++)
                wv[i] = *reinterpret_cast<const float4*>(wp[i] + off);
#pragma unroll
            for (int bb = 0; bb < 8; bb++) {
                float4 a4 = *reinterpret_cast<const float4*>(ap[bb] + off);
                float2 alo = make_float2(a4.x, a4.y);
                float2 ahi = make_float2(a4.z, a4.w);
#pragma unroll
                for (int jj = 0; jj < 2; jj++) {
                    fma2(ar[jj][bb], alo, make_float2(wv[0 + jj].x, wv[0 + jj].y));
                    fma2(ar[jj][bb], ahi, make_float2(wv[0 + jj].z, wv[0 + jj].w));
                    fma2(az[jj][bb], alo, make_float2(wv[2 + jj].x, wv[2 + jj].y));
                    fma2(az[jj][bb], ahi, make_float2(wv[2 + jj].z, wv[2 + jj].w));
                    fma2(an[jj][bb], alo, make_float2(wv[4 + jj].x, wv[4 + jj].y));
                    fma2(an[jj][bb], ahi, make_float2(wv[4 + jj].z, wv[4 + jj].w));
                }
            }
        }
#pragma unroll
        for (int bb = 0; bb < 8; bb++) ap[bb] += 128;
#pragma unroll
        for (int i = 0; i < 6; i++) wp[i] += 128;
    }
}

// GRU gate epilogue: reduce k-slices, apply gates, write h'.
__device__ __forceinline__ void gru_epilogue(
    float2 (&ar)[2][8], float2 (&az)[2][8],
    float2 (&ain)[2][8], float2 (&ahn)[2][8],
    const float (&bs)[2][4],
    const float* __restrict__ hprev, float* __restrict__ hout,
    int j0, int b0, int lane)
{
#pragma unroll
    for (int jj = 0; jj < 2; jj++) {
#pragma unroll
        for (int bb = 0; bb < 8; bb++) {
            float rr = redk(ar[jj][bb]);
            float zz = redk(az[jj][bb]);
            float ii = redk(ain[jj][bb]);
            float hh = redk(ahn[jj][bb]);
            if (lane < 4) {
                int j = j0 + jj;
                int b = b0 + bb;
                float r = sigf(rr + bs[jj][0]);
                float z = sigf(zz + bs[jj][1]);
                float n = tanh_(ii + bs[jj][2] + r * (hh + bs[jj][3]));
                float hp = hprev[(size_t)b * H + j];
                hout[(size_t)b * H + j] = n + z * (hp - n);
            }
        }
    }
}

__global__ void __launch_bounds__(NT, 1) gru_persistent(
    const float* __restrict__ x,
    const float* __restrict__ Wi0, const float* __restrict__ Wh0,
    const float* __restrict__ bi0, const float* __restrict__ bh0,
    const float* __restrict__ Wi1, const float* __restrict__ Wh1,
    const float* __restrict__ bi1, const float* __restrict__ bh1,
    const float* __restrict__ Wo,  const float* __restrict__ bo,
    float* __restrict__ out)
{
    const int tid   = threadIdx.x;
    const int lane  = tid & 31;
    const int warp  = tid >> 5;
    const int jgrp  = lane & 3;
    const int s     = lane >> 2;
    const int b0    = warp * 8;
    const int jbase = blockIdx.x * 8;
    const int j0    = jbase + jgrp * 2;

    // Zero initial state buffers (buffer 0 only; buffer 1 is written before read)
    for (int i = blockIdx.x * NT + tid; i < B * H; i += NCTA * NT) {
        g_h0[0][i] = 0.0f;
        g_h1[0][i] = 0.0f;
    }

    // Preload bias sums for this thread's two j's, both layers
    float bs0[2][4], bs1[2][4];
#pragma unroll
    for (int jj = 0; jj < 2; jj++) {
        int j = j0 + jj;
        bs0[jj][0] = bi0[j] + bh0[j];
        bs0[jj][1] = bi0[H + j] + bh0[H + j];
        bs0[jj][2] = bi0[2 * H + j];
        bs0[jj][3] = bh0[2 * H + j];
        bs1[jj][0] = bi1[j] + bh1[j];
        bs1[jj][1] = bi1[H + j] + bh1[H + j];
        bs1[jj][2] = bi1[2 * H + j];
        bs1[jj][3] = bh1[2 * H + j];
    }

    unsigned gen = 0;
    grid_sync(++gen * NCTA);   // h init visible everywhere

    for (int t = 0; t < T; t++) {
        const int pp = t & 1, cc = pp ^ 1;
        const float* h0p = g_h0[pp];
        float*       h0n = g_h0[cc];
        const float* h1p = g_h1[pp];
        float*       h1n = g_h1[cc];

        float2 ar[2][8], az[2][8], ain[2][8], ahn[2][8];
#pragma unroll
        for (int jj = 0; jj < 2; jj++)
#pragma unroll
            for (int bb = 0; bb < 8; bb++) {
                ar[jj][bb] = make_float2(0.f, 0.f);
                az[jj][bb] = make_float2(0.f, 0.f);
                ain[jj][bb] = make_float2(0.f, 0.f);
                ahn[jj][bb] = make_float2(0.f, 0.f);
            }

        // Layer 0: gi = x_t @ Wi0^T ; gh = h0 @ Wh0^T
        gemm_phase<DIN, T * DIN>(x + (size_t)t * DIN, Wi0, j0, s, b0, ar, az, ain);
        gemm_phase<H, H>(h0p, Wh0, j0, s, b0, ar, az, ahn);
        gru_epilogue(ar, az, ain, ahn, bs0, h0p, h0n, j0, b0, lane);

        grid_sync(++gen * NCTA);   // h0' visible

        // Layer 1: gi = h0' @ Wi1^T ; gh = h1 @ Wh1^T
#pragma unroll
        for (int jj = 0; jj < 2; jj++)
#pragma unroll
            for (int bb = 0; bb < 8; bb++) {
                ar[jj][bb] = make_float2(0.f, 0.f);
                az[jj][bb] = make_float2(0.f, 0.f);
                ain[jj][bb] = make_float2(0.f, 0.f);
                ahn[jj][bb] = make_float2(0.f, 0.f);
            }
        gemm_phase<H, H>(h0n, Wi1, j0, s, b0, ar, az, ain);
        gemm_phase<H, H>(h1p, Wh1, j0, s, b0, ar, az, ahn);
        gru_epilogue(ar, az, ain, ahn, bs1, h1p, h1n, j0, b0, lane);

        grid_sync(++gen * NCTA);   // h1' visible
    }

    // Output projection: out[b, o] = h1_final[b,:] . Wo[o,:] + bo[o]
    // h1 final lives in g_h1[0] (t=511 wrote buffer 0). CTA handles o = 2*bid, 2*bid+1.
    {
        __shared__ float red[NT];
        const int e  = tid & 127;
        const int kh = tid >> 7;
        const int b  = e & 63;
        const int o  = blockIdx.x * 2 + (e >> 6);
        const float* w  = Wo + (size_t)o * H + kh * 512;
        const float* hh = g_h1[0] + (size_t)b * H + kh * 512;
        float2 acc = make_float2(0.f, 0.f);
#pragma unroll 8
        for (int k = 0; k < 512; k += 4) {
            float4 wv = *reinterpret_cast<const float4*>(w + k);
            float4 hv = *reinterpret_cast<const float4*>(hh + k);
            fma2(acc, make_float2(hv.x, hv.y), make_float2(wv.x, wv.y));
            fma2(acc, make_float2(hv.z, hv.w), make_float2(wv.z, wv.w));
        }
        red[tid] = acc.x + acc.y;
        __syncthreads();
        if (tid < 128) {
            out[(size_t)b * DOUT + o] = red[tid] + red[tid + 128] + bo[o];
        }
    }

    // Reset barrier counters for the next launch. The last CTA to arrive here
    // is ordered after every CTA has exited its final spin, so this is race-free.
    __syncthreads();
    if (tid == 0) {
        unsigned old = atomicAdd(&g_done, 1u);
        if (old == NCTA - 1u) {
            g_bar_count = 0u;
            g_done = 0u;
            __threadfence();
        }
    }
}

extern "C" void kernel_launch(void* const* d_in, const int* in_sizes, int n_in,
                              void* d_out, int out_size)
{
    const float* x   = (const float*)d_in[0];
    const float* Wi0 = (const float*)d_in[1];
    const float* Wh0 = (const float*)d_in[2];
    const float* bi0 = (const float*)d_in[3];
    const float* bh0 = (const float*)d_in[4];
    const float* Wi1 = (const float*)d_in[5];
    const float* Wh1 = (const float*)d_in[6];
    const float* bi1 = (const float*)d_in[7];
    const float* bh1 = (const float*)d_in[8];
    const float* Wo  = (const float*)d_in[9];
    const float* bo  = (const float*)d_in[10];
    float* out = (float*)d_out;

    gru_persistent<<<NCTA, NT>>>(x, Wi0, Wh0, bi0, bh0,
                                 Wi1, Wh1, bi1, bh1, Wo, bo, out);
}

// round 5
// speedup vs baseline: 2.4586x; 2.4535x over previous
#include <cuda_runtime.h>
#include <cuda_bf16.h>

#define B_   64
#define T_   512
#define DIN  256
#define H_   1024
#define DOUT 256
#define NCTA 128
#define NT   128

constexpr int KT0 = DIN / 16;   // 16 k-groups (Wi0)
constexpr int KTH = H_ / 16;    // 64 k-groups (Wh0/Wi1/Wh1)
constexpr size_t FSZ0 = (size_t)64 * 3 * KT0 * 64;
constexpr size_t FSZH = (size_t)64 * 3 * KTH * 64;
constexpr size_t FB0 = 0, FB1 = FSZ0, FB2 = FSZ0 + FSZH, FB3 = FSZ0 + 2 * FSZH;

__device__ uint4 g_wA[FSZ0 + 3 * FSZH];                 // ~41 MB frag table
__device__ float g_h0f[2][B_ * H_], g_h1f[2][B_ * H_];  // fp32 carry
__device__ __nv_bfloat16 g_h0h[2][B_ * H_], g_h0l[2][B_ * H_];
__device__ __nv_bfloat16 g_h1h[2][B_ * H_], g_h1l[2][B_ * H_];
__device__ __nv_bfloat16 g_xh[T_ * B_ * DIN], g_xl[T_ * B_ * DIN];
__device__ unsigned g_bar, g_done;

__device__ __forceinline__ unsigned short bfbits(float v) {
    __nv_bfloat16 b = __float2bfloat16_rn(v);
    return *reinterpret_cast<unsigned short*>(&b);
}
__device__ __forceinline__ float bf2f(unsigned short u) {
    __nv_bfloat16 b = *reinterpret_cast<__nv_bfloat16*>(&u);
    return __bfloat162float(b);
}
__device__ __forceinline__ unsigned pk(float a, float b) {
    return (unsigned)bfbits(a) | ((unsigned)bfbits(b) << 16);
}
__device__ __forceinline__ float resid(float w) { return w - bf2f(bfbits(w)); }
__device__ __forceinline__ float sigf(float x) {
    return __fdividef(1.0f, 1.0f + __expf(-x));
}
__device__ __forceinline__ float tanh_(float x) {
    return __fdividef(2.0f, 1.0f + __expf(-2.0f * x)) - 1.0f;
}

__device__ __forceinline__ void mma16816(float (&d)[4], const uint4 a,
                                         unsigned b0, unsigned b1) {
    asm volatile(
        "mma.sync.aligned.m16n8k16.row.col.f32.bf16.bf16.f32 "
        "{%0,%1,%2,%3},{%4,%5,%6,%7},{%8,%9},{%0,%1,%2,%3};"
        : "+f"(d[0]), "+f"(d[1]), "+f"(d[2]), "+f"(d[3])
        : "r"(a.x), "r"(a.y), "r"(a.z), "r"(a.w), "r"(b0), "r"(b1));
}

__device__ __forceinline__ void grid_sync(unsigned gen) {
    __syncthreads();
    if (threadIdx.x == 0) {
        __threadfence();
        atomicAdd(&g_bar, 1u);
        while (*((volatile unsigned*)&g_bar) < gen * NCTA) { }
        __threadfence();
    }
    __syncthreads();
}

// acc += W_frag x act over K. fA pre-offset by (jt, lane). Chains [0]=hi*hi, [1]=mixed.
template<int K>
__device__ __forceinline__ void run_phase(
    const uint4* __restrict__ fA,
    const __nv_bfloat16* __restrict__ aH, const __nv_bfloat16* __restrict__ aL,
    int n0, int lane,
    float (&aR)[2][4], float (&aZ)[2][4], float (&aN)[2][4])
{
    constexpr int KT = K / 16;
    const unsigned* bh = reinterpret_cast<const unsigned*>(
        aH + (size_t)(n0 + (lane >> 2)) * K) + (lane & 3);
    const unsigned* bl = reinterpret_cast<const unsigned*>(
        aL + (size_t)(n0 + (lane >> 2)) * K) + (lane & 3);
#pragma unroll 4
    for (int kg = 0; kg < KT; ++kg) {
        unsigned bh0 = bh[0], bh1 = bh[4];
        unsigned bl0 = bl[0], bl1 = bl[4];
        uint4 A0h = fA[(0 * KT + kg) * 64], A0l = fA[(0 * KT + kg) * 64 + 32];
        uint4 A1h = fA[(1 * KT + kg) * 64], A1l = fA[(1 * KT + kg) * 64 + 32];
        uint4 A2h = fA[(2 * KT + kg) * 64], A2l = fA[(2 * KT + kg) * 64 + 32];
        mma16816(aR[0], A0h, bh0, bh1);
        mma16816(aZ[0], A1h, bh0, bh1);
        mma16816(aN[0], A2h, bh0, bh1);
        mma16816(aR[1], A0h, bl0, bl1);
        mma16816(aZ[1], A1h, bl0, bl1);
        mma16816(aN[1], A2h, bl0, bl1);
        mma16816(aR[1], A0l, bh0, bh1);
        mma16816(aZ[1], A1l, bh0, bh1);
        mma16816(aN[1], A2l, bh0, bh1);
        bh += 8; bl += 8;
    }
}

__device__ __forceinline__ void epi(
    float (&aR)[2][4], float (&aZ)[2][4], float (&aNi)[2][4], float (&aNh)[2][4],
    const float (&bR)[2], const float (&bZ)[2], const float (&bI)[2], const float (&bN)[2],
    const float* __restrict__ hpf, float* __restrict__ hf,
    __nv_bfloat16* __restrict__ hhi, __nv_bfloat16* __restrict__ hlo,
    int j0, int n0, int lane)
{
    const int jm = j0 + (lane >> 2);
    const int bb = n0 + 2 * (lane & 3);
#pragma unroll
    for (int e = 0; e < 4; ++e) {
        const int q = e >> 1;               // 0: row jm, 1: row jm+8
        const int j = jm + 8 * q;
        const int b = bb + (e & 1);
        float r = sigf(aR[0][e] + aR[1][e] + bR[q]);
        float z = sigf(aZ[0][e] + aZ[1][e] + bZ[q]);
        float n = tanh_(aNi[0][e] + aNi[1][e] + bI[q] +
                        r * (aNh[0][e] + aNh[1][e] + bN[q]));
        size_t o = (size_t)b * H_ + j;
        float h = n + z * (hpf[o] - n);
        hf[o] = h;
        unsigned short u = bfbits(h);
        hhi[o] = *reinterpret_cast<__nv_bfloat16*>(&u);
        hlo[o] = __float2bfloat16_rn(h - bf2f(u));
    }
}

__global__ void __launch_bounds__(NT, 1) gru_tc(
    const float* __restrict__ x,
    const float* __restrict__ Wi0, const float* __restrict__ Wh0,
    const float* __restrict__ bi0, const float* __restrict__ bh0,
    const float* __restrict__ Wi1, const float* __restrict__ Wh1,
    const float* __restrict__ bi1, const float* __restrict__ bh1,
    const float* __restrict__ Wo,  const float* __restrict__ bo,
    float* __restrict__ out)
{
    const int tid = threadIdx.x, lane = tid & 31, warp = tid >> 5, cta = blockIdx.x;
    const int jt = cta >> 1;
    const int j0 = jt * 16;
    const int n0 = (cta & 1) * 32 + warp * 8;

    // ---- one-time prep: x -> bf16 hi/lo in [t][b][k] ----
    for (size_t i = (size_t)cta * NT + tid; i < (size_t)T_ * B_ * DIN;
         i += (size_t)NCTA * NT) {
        int k = (int)(i & (DIN - 1));
        int b = (int)((i >> 8) & 63);
        int t = (int)(i >> 14);
        float v = x[((size_t)b * T_ + t) * DIN + k];
        unsigned short u = bfbits(v);
        g_xh[i] = *reinterpret_cast<__nv_bfloat16*>(&u);
        g_xl[i] = __float2bfloat16_rn(v - bf2f(u));
    }
    // ---- zero initial state (buffer 0) ----
    for (int i = cta * NT + tid; i < B_ * H_; i += NCTA * NT) {
        g_h0f[0][i] = 0.f; g_h1f[0][i] = 0.f;
        __nv_bfloat16 z = __float2bfloat16_rn(0.f);
        g_h0h[0][i] = z; g_h0l[0][i] = z; g_h1h[0][i] = z; g_h1l[0][i] = z;
    }
    // ---- weights -> fragment-direct split-bf16 table ----
    {
        const float* Wp[4] = { Wi0, Wh0, Wi1, Wh1 };
        const int    Kp[4] = { DIN, H_, H_, H_ };
        const size_t Fp[4] = { FB0, FB1, FB2, FB3 };
        for (int p = 0; p < 4; ++p) {
            const int K = Kp[p], KT = K / 16;
            const float* W = Wp[p];
            const int total = 64 * 3 * KT * 32;
            for (int i = cta * NT + tid; i < total; i += NCTA * NT) {
                int l = i & 31;
                int item = i >> 5;
                int kg = item % KT;
                int g = (item / KT) % 3;
                int jtt = item / (KT * 3);
                int m = l >> 2, kb = 2 * (l & 3);
                const float* r0 = W + (size_t)(g * H_ + jtt * 16 + m) * K + kg * 16 + kb;
                const float* r1 = r0 + 8 * (size_t)K;
                float w00 = r0[0], w01 = r0[1], w02 = r0[8], w03 = r0[9];
                float w10 = r1[0], w11 = r1[1], w12 = r1[8], w13 = r1[9];
                uint4 hv, lv;
                hv.x = pk(w00, w01); hv.y = pk(w10, w11);
                hv.z = pk(w02, w03); hv.w = pk(w12, w13);
                lv.x = pk(resid(w00), resid(w01)); lv.y = pk(resid(w10), resid(w11));
                lv.z = pk(resid(w02), resid(w03)); lv.w = pk(resid(w12), resid(w13));
                size_t base = Fp[p] + ((size_t)(jtt * 3 + g) * KT + kg) * 64;
                g_wA[base + l] = hv;
                g_wA[base + 32 + l] = lv;
            }
        }
    }
    // ---- biases for this thread's two j rows ----
    float bR0[2], bZ0[2], bI0[2], bN0[2], bR1[2], bZ1[2], bI1[2], bN1[2];
    const int jm = j0 + (lane >> 2);
#pragma unroll
    for (int q = 0; q < 2; ++q) {
        int j = jm + 8 * q;
        bR0[q] = bi0[j] + bh0[j];
        bZ0[q] = bi0[H_ + j] + bh0[H_ + j];
        bI0[q] = bi0[2 * H_ + j];
        bN0[q] = bh0[2 * H_ + j];
        bR1[q] = bi1[j] + bh1[j];
        bZ1[q] = bi1[H_ + j] + bh1[H_ + j];
        bI1[q] = bi1[2 * H_ + j];
        bN1[q] = bh1[2 * H_ + j];
    }

    const uint4* fWi0 = g_wA + FB0 + (size_t)jt * 3 * KT0 * 64 + lane;
    const uint4* fWh0 = g_wA + FB1 + (size_t)jt * 3 * KTH * 64 + lane;
    const uint4* fWi1 = g_wA + FB2 + (size_t)jt * 3 * KTH * 64 + lane;
    const uint4* fWh1 = g_wA + FB3 + (size_t)jt * 3 * KTH * 64 + lane;

    unsigned gen = 0;
    grid_sync(++gen);   // prep visible

    for (int t = 0; t < T_; ++t) {
        const int pp = t & 1, cc = pp ^ 1;
        {
            float aR[2][4] = {}, aZ[2][4] = {}, aNi[2][4] = {}, aNh[2][4] = {};
            run_phase<DIN>(fWi0, g_xh + (size_t)t * B_ * DIN,
                           g_xl + (size_t)t * B_ * DIN, n0, lane, aR, aZ, aNi);
            run_phase<H_>(fWh0, g_h0h[pp], g_h0l[pp], n0, lane, aR, aZ, aNh);
            epi(aR, aZ, aNi, aNh, bR0, bZ0, bI0, bN0,
                g_h0f[pp], g_h0f[cc], g_h0h[cc], g_h0l[cc], j0, n0, lane);
        }
        grid_sync(++gen);   // h0' visible
        {
            float aR[2][4] = {}, aZ[2][4] = {}, aNi[2][4] = {}, aNh[2][4] = {};
            run_phase<H_>(fWi1, g_h0h[cc], g_h0l[cc], n0, lane, aR, aZ, aNi);
            run_phase<H_>(fWh1, g_h1h[pp], g_h1l[pp], n0, lane, aR, aZ, aNh);
            epi(aR, aZ, aNi, aNh, bR1, bZ1, bI1, bN1,
                g_h1f[pp], g_h1f[cc], g_h1h[cc], g_h1l[cc], j0, n0, lane);
        }
        grid_sync(++gen);   // h1' visible
    }

    // ---- output projection: out[b,o] = h1_final[b,:] . Wo[o,:] + bo[o] ----
    {
        const float* h1 = g_h1f[0];      // t=511 wrote buffer 0
        const int o = cta * 2 + (tid >> 6);
        const int b = tid & 63;
        const float* w  = Wo + (size_t)o * H_;
        const float* hv = h1 + (size_t)b * H_;
        float acc = 0.f;
#pragma unroll 4
        for (int k = 0; k < H_; k += 4) {
            float4 wv = *reinterpret_cast<const float4*>(w + k);
            float4 h4 = *reinterpret_cast<const float4*>(hv + k);
            acc += wv.x * h4.x + wv.y * h4.y + wv.z * h4.z + wv.w * h4.w;
        }
        out[(size_t)b * DOUT + o] = acc + bo[o];
    }

    // ---- reset barrier counters for next replay ----
    __syncthreads();
    if (tid == 0) {
        unsigned old = atomicAdd(&g_done, 1u);
        if (old == NCTA - 1u) {
            g_bar = 0u;
            g_done = 0u;
            __threadfence();
        }
    }
}

extern "C" void kernel_launch(void* const* d_in, const int* in_sizes, int n_in,
                              void* d_out, int out_size)
{
    gru_tc<<<NCTA, NT>>>(
        (const float*)d_in[0], (const float*)d_in[1], (const float*)d_in[2],
        (const float*)d_in[3], (const float*)d_in[4], (const float*)d_in[5],
        (const float*)d_in[6], (const float*)d_in[7], (const float*)d_in[8],
        (const float*)d_in[9], (const float*)d_in[10], (float*)d_out);
}

// round 6
// speedup vs baseline: 3.6272x; 1.4753x over previous
#include <cuda_runtime.h>
#include <cuda_bf16.h>

#define B_   64
#define T_   512
#define DIN  256
#define H_   1024
#define DOUT 256
#define NCTA 128
#define NT   256

constexpr int KT0 = DIN / 16;   // 16 k-groups (Wi0)
constexpr int KTH = H_ / 16;    // 64 k-groups (others)
constexpr size_t FSZ0 = (size_t)64 * 3 * KT0 * 64;
constexpr size_t FSZH = (size_t)64 * 3 * KTH * 64;
constexpr size_t FB0 = 0, FB1 = FSZ0, FB2 = FSZ0 + FSZH, FB3 = FSZ0 + 2 * FSZH;

__device__ uint4 g_wA[FSZ0 + 3 * FSZH];                 // ~41 MB frag table
__device__ float g_h0f[2][B_ * H_], g_h1f[2][B_ * H_];  // fp32 carry
__device__ __nv_bfloat16 g_h0h[2][B_ * H_], g_h0l[2][B_ * H_];
__device__ __nv_bfloat16 g_h1h[2][B_ * H_], g_h1l[2][B_ * H_];
__device__ __nv_bfloat16 g_xh[T_ * B_ * DIN], g_xl[T_ * B_ * DIN];
__device__ unsigned g_bar, g_done;

__device__ __forceinline__ unsigned short bfbits(float v) {
    __nv_bfloat16 b = __float2bfloat16_rn(v);
    return *reinterpret_cast<unsigned short*>(&b);
}
__device__ __forceinline__ float bf2f(unsigned short u) {
    __nv_bfloat16 b = *reinterpret_cast<__nv_bfloat16*>(&u);
    return __bfloat162float(b);
}
__device__ __forceinline__ unsigned pk(float a, float b) {
    return (unsigned)bfbits(a) | ((unsigned)bfbits(b) << 16);
}
__device__ __forceinline__ float resid(float w) { return w - bf2f(bfbits(w)); }
__device__ __forceinline__ float sigf(float x) {
    return __fdividef(1.0f, 1.0f + __expf(-x));
}
__device__ __forceinline__ float tanh_(float x) {
    return __fdividef(2.0f, 1.0f + __expf(-2.0f * x)) - 1.0f;
}

__device__ __forceinline__ void mma16816(float (&d)[4], const uint4 a,
                                         unsigned b0, unsigned b1) {
    asm volatile(
        "mma.sync.aligned.m16n8k16.row.col.f32.bf16.bf16.f32 "
        "{%0,%1,%2,%3},{%4,%5,%6,%7},{%8,%9},{%0,%1,%2,%3};"
        : "+f"(d[0]), "+f"(d[1]), "+f"(d[2]), "+f"(d[3])
        : "r"(a.x), "r"(a.y), "r"(a.z), "r"(a.w), "r"(b0), "r"(b1));
}

__device__ __forceinline__ void grid_sync(unsigned gen) {
    __syncthreads();
    if (threadIdx.x == 0) {
        __threadfence();
        atomicAdd(&g_bar, 1u);
        while (*((volatile unsigned*)&g_bar) < gen * NCTA) { }
        __threadfence();
    }
    __syncthreads();
}

// acc += W_frag x act over kg in [kg0, kg0+kgn). Warp covers 16 batch rows
// (2 n8-pairs). fA pre-offset by (jt, lane). Chains: [0]=hi*hi, [1]=mixed.
template<int K>
__device__ __forceinline__ void run_phase(
    const uint4* __restrict__ fA,
    const __nv_bfloat16* __restrict__ aH, const __nv_bfloat16* __restrict__ aL,
    int n0, int lane, int kg0, int kgn,
    float (&aR)[2][2][4], float (&aZ)[2][2][4], float (&aN)[2][2][4])
{
    constexpr int KT = K / 16;
    constexpr int RS = K / 2;  // row stride in 32-bit units
    const unsigned* bh = reinterpret_cast<const unsigned*>(aH)
                         + (size_t)(n0 + (lane >> 2)) * RS + (lane & 3) + kg0 * 8;
    const unsigned* bl = reinterpret_cast<const unsigned*>(aL)
                         + (size_t)(n0 + (lane >> 2)) * RS + (lane & 3) + kg0 * 8;
#pragma unroll 4
    for (int kg = kg0; kg < kg0 + kgn; ++kg) {
        unsigned b0h[2], b1h[2], b0l[2], b1l[2];
#pragma unroll
        for (int p = 0; p < 2; ++p) {
            b0h[p] = bh[p * 8 * RS];     b1h[p] = bh[p * 8 * RS + 4];
            b0l[p] = bl[p * 8 * RS];     b1l[p] = bl[p * 8 * RS + 4];
        }
        uint4 A0h = fA[(0 * KT + kg) * 64], A0l = fA[(0 * KT + kg) * 64 + 32];
        uint4 A1h = fA[(1 * KT + kg) * 64], A1l = fA[(1 * KT + kg) * 64 + 32];
        uint4 A2h = fA[(2 * KT + kg) * 64], A2l = fA[(2 * KT + kg) * 64 + 32];
#pragma unroll
        for (int p = 0; p < 2; ++p) {
            mma16816(aR[0][p], A0h, b0h[p], b1h[p]);
            mma16816(aZ[0][p], A1h, b0h[p], b1h[p]);
            mma16816(aN[0][p], A2h, b0h[p], b1h[p]);
            mma16816(aR[1][p], A0h, b0l[p], b1l[p]);
            mma16816(aZ[1][p], A1h, b0l[p], b1l[p]);
            mma16816(aN[1][p], A2h, b0l[p], b1l[p]);
        }
#pragma unroll
        for (int p = 0; p < 2; ++p) {
            mma16816(aR[1][p], A0l, b0h[p], b1h[p]);
            mma16816(aZ[1][p], A1l, b0h[p], b1h[p]);
            mma16816(aN[1][p], A2l, b0h[p], b1h[p]);
        }
        bh += 8; bl += 8;
    }
}

// 4-way k-quarter reduce through SMEM, then gate epilogue on ks==0 warps.
__device__ __forceinline__ void reduce_epi(
    float (&aR)[2][2][4], float (&aZ)[2][2][4],
    float (&aNi)[2][2][4], float (&aNh)[2][2][4],
    const float* bR, const float* bZ, const float* bI, const float* bN,
    const float* __restrict__ hpf, float* __restrict__ hf,
    __nv_bfloat16* __restrict__ hhi, __nv_bfloat16* __restrict__ hlo,
    int j0, int n0, int lane, int nw, int ks,
    float (*rbuf)[2][32][32])
{
    float v[32];
#pragma unroll
    for (int p = 0; p < 2; ++p)
#pragma unroll
        for (int e = 0; e < 4; ++e) {
            v[0  + p * 4 + e] = aR[0][p][e]  + aR[1][p][e];
            v[8  + p * 4 + e] = aZ[0][p][e]  + aZ[1][p][e];
            v[16 + p * 4 + e] = aNi[0][p][e] + aNi[1][p][e];
            v[24 + p * 4 + e] = aNh[0][p][e] + aNh[1][p][e];
        }
    if (ks) {
#pragma unroll
        for (int i = 0; i < 32; ++i) rbuf[ks - 1][nw][i][lane] = v[i];
    }
    __syncthreads();
    if (ks == 0) {
#pragma unroll
        for (int q = 0; q < 3; ++q)
#pragma unroll
            for (int i = 0; i < 32; ++i) v[i] += rbuf[q][nw][i][lane];
#pragma unroll
        for (int p = 0; p < 2; ++p)
#pragma unroll
            for (int e = 0; e < 4; ++e) {
                const int q = e >> 1;
                const int j = j0 + (lane >> 2) + 8 * q;
                const int b = n0 + 8 * p + 2 * (lane & 3) + (e & 1);
                float r = sigf(v[0 + p * 4 + e] + bR[q]);
                float z = sigf(v[8 + p * 4 + e] + bZ[q]);
                float n = tanh_(v[16 + p * 4 + e] + bI[q] +
                                r * (v[24 + p * 4 + e] + bN[q]));
                size_t o = (size_t)b * H_ + j;
                float h = n + z * (hpf[o] - n);
                hf[o] = h;
                unsigned short u = bfbits(h);
                hhi[o] = *reinterpret_cast<__nv_bfloat16*>(&u);
                hlo[o] = __float2bfloat16_rn(h - bf2f(u));
            }
    }
    __syncthreads();
}

__global__ void __launch_bounds__(NT, 1) gru_tc(
    const float* __restrict__ x,
    const float* __restrict__ Wi0, const float* __restrict__ Wh0,
    const float* __restrict__ bi0, const float* __restrict__ bh0,
    const float* __restrict__ Wi1, const float* __restrict__ Wh1,
    const float* __restrict__ bi1, const float* __restrict__ bh1,
    const float* __restrict__ Wo,  const float* __restrict__ bo,
    float* __restrict__ out)
{
    __shared__ float rbuf[3][2][32][32];   // 24 KB k-quarter reduce buffer

    const int tid = threadIdx.x, lane = tid & 31, warp = tid >> 5, cta = blockIdx.x;
    const int jt = cta >> 1;
    const int j0 = jt * 16;
    const int nw = warp & 1;       // n-tile within the 32-batch half
    const int ks = warp >> 1;      // k-quarter 0..3
    const int n0 = (cta & 1) * 32 + nw * 16;

    // ---- one-time prep: x -> bf16 hi/lo in [t][b][k] ----
    for (size_t i = (size_t)cta * NT + tid; i < (size_t)T_ * B_ * DIN;
         i += (size_t)NCTA * NT) {
        int k = (int)(i & (DIN - 1));
        int b = (int)((i >> 8) & 63);
        int t = (int)(i >> 14);
        float v = x[((size_t)b * T_ + t) * DIN + k];
        unsigned short u = bfbits(v);
        g_xh[i] = *reinterpret_cast<__nv_bfloat16*>(&u);
        g_xl[i] = __float2bfloat16_rn(v - bf2f(u));
    }
    // ---- zero initial state (buffer 1: read at phase 0 / 1) ----
    for (int i = cta * NT + tid; i < B_ * H_; i += NCTA * NT) {
        g_h0f[1][i] = 0.f; g_h1f[1][i] = 0.f;
        __nv_bfloat16 z = __float2bfloat16_rn(0.f);
        g_h0h[1][i] = z; g_h0l[1][i] = z; g_h1h[1][i] = z; g_h1l[1][i] = z;
    }
    // ---- weights -> fragment-direct split-bf16 table ----
    {
        const float* Wp[4] = { Wi0, Wh0, Wi1, Wh1 };
        const int    Kp[4] = { DIN, H_, H_, H_ };
        const size_t Fp[4] = { FB0, FB1, FB2, FB3 };
        for (int p = 0; p < 4; ++p) {
            const int K = Kp[p], KT = K / 16;
            const float* W = Wp[p];
            const int total = 64 * 3 * KT * 32;
            for (int i = cta * NT + tid; i < total; i += NCTA * NT) {
                int l = i & 31;
                int item = i >> 5;
                int kg = item % KT;
                int g = (item / KT) % 3;
                int jtt = item / (KT * 3);
                int m = l >> 2, kb = 2 * (l & 3);
                const float* r0 = W + (size_t)(g * H_ + jtt * 16 + m) * K + kg * 16 + kb;
                const float* r1 = r0 + 8 * (size_t)K;
                float w00 = r0[0], w01 = r0[1], w02 = r0[8], w03 = r0[9];
                float w10 = r1[0], w11 = r1[1], w12 = r1[8], w13 = r1[9];
                uint4 hv, lv;
                hv.x = pk(w00, w01); hv.y = pk(w10, w11);
                hv.z = pk(w02, w03); hv.w = pk(w12, w13);
                lv.x = pk(resid(w00), resid(w01)); lv.y = pk(resid(w10), resid(w11));
                lv.z = pk(resid(w02), resid(w03)); lv.w = pk(resid(w12), resid(w13));
                size_t base = Fp[p] + ((size_t)(jtt * 3 + g) * KT + kg) * 64;
                g_wA[base + l] = hv;
                g_wA[base + 32 + l] = lv;
            }
        }
    }
    // ---- biases for this lane's two j rows ----
    float bR0[2], bZ0[2], bI0[2], bN0[2], bR1[2], bZ1[2], bI1[2], bN1[2];
    const int jm = j0 + (lane >> 2);
#pragma unroll
    for (int q = 0; q < 2; ++q) {
        int j = jm + 8 * q;
        bR0[q] = bi0[j] + bh0[j];
        bZ0[q] = bi0[H_ + j] + bh0[H_ + j];
        bI0[q] = bi0[2 * H_ + j];
        bN0[q] = bh0[2 * H_ + j];
        bR1[q] = bi1[j] + bh1[j];
        bZ1[q] = bi1[H_ + j] + bh1[H_ + j];
        bI1[q] = bi1[2 * H_ + j];
        bN1[q] = bh1[2 * H_ + j];
    }

    const uint4* fWi0 = g_wA + FB0 + (size_t)jt * 3 * KT0 * 64 + lane;
    const uint4* fWh0 = g_wA + FB1 + (size_t)jt * 3 * KTH * 64 + lane;
    const uint4* fWi1 = g_wA + FB2 + (size_t)jt * 3 * KTH * 64 + lane;
    const uint4* fWh1 = g_wA + FB3 + (size_t)jt * 3 * KTH * 64 + lane;

    unsigned gen = 0;
    grid_sync(++gen);   // prep visible

    // Software-pipelined phases: phase p = layer0(t=p) || layer1(t=p-1).
    // h0(t) lives in buffer t&1; h1(t) lives in buffer t&1.
    for (int p = 0; p <= T_; ++p) {
        const int w0 = p & 1, r0 = w0 ^ 1;          // layer0 h0 write/read bufs
        const int w1 = (p + 1) & 1, r1 = p & 1;     // layer1 h1 write/read bufs
        if (p < T_) {
            float aR[2][2][4] = {}, aZ[2][2][4] = {}, aNi[2][2][4] = {}, aNh[2][2][4] = {};
            run_phase<DIN>(fWi0, g_xh + (size_t)p * B_ * DIN,
                           g_xl + (size_t)p * B_ * DIN, n0, lane, ks * 4, 4,
                           aR, aZ, aNi);
            run_phase<H_>(fWh0, g_h0h[r0], g_h0l[r0], n0, lane, ks * 16, 16,
                          aR, aZ, aNh);
            reduce_epi(aR, aZ, aNi, aNh, bR0, bZ0, bI0, bN0,
                       g_h0f[r0], g_h0f[w0], g_h0h[w0], g_h0l[w0],
                       j0, n0, lane, nw, ks, rbuf);
        }
        if (p > 0) {
            float aR[2][2][4] = {}, aZ[2][2][4] = {}, aNi[2][2][4] = {}, aNh[2][2][4] = {};
            // layer1(t=p-1): input h0(p-1) = buffer (p-1)&1 = w1
            run_phase<H_>(fWi1, g_h0h[w1], g_h0l[w1], n0, lane, ks * 16, 16,
                          aR, aZ, aNi);
            run_phase<H_>(fWh1, g_h1h[r1], g_h1l[r1], n0, lane, ks * 16, 16,
                          aR, aZ, aNh);
            reduce_epi(aR, aZ, aNi, aNh, bR1, bZ1, bI1, bN1,
                       g_h1f[r1], g_h1f[w1], g_h1h[w1], g_h1l[w1],
                       j0, n0, lane, nw, ks, rbuf);
        }
        grid_sync(++gen);
    }

    // ---- output projection: out[b,o] = h1(511)[b,:] . Wo[o,:] + bo[o] ----
    // h1(511) is in buffer 511&1 = 1.
    if (tid < 128) {
        const float* h1 = g_h1f[1];
        const int o = cta * 2 + (tid >> 6);
        const int b = tid & 63;
        const float* w  = Wo + (size_t)o * H_;
        const float* hv = h1 + (size_t)b * H_;
        float acc = 0.f;
#pragma unroll 4
        for (int k = 0; k < H_; k += 4) {
            float4 wv = *reinterpret_cast<const float4*>(w + k);
            float4 h4 = *reinterpret_cast<const float4*>(hv + k);
            acc += wv.x * h4.x + wv.y * h4.y + wv.z * h4.z + wv.w * h4.w;
        }
        out[(size_t)b * DOUT + o] = acc + bo[o];
    }

    // ---- reset barrier counters for next replay ----
    __syncthreads();
    if (tid == 0) {
        unsigned old = atomicAdd(&g_done, 1u);
        if (old == NCTA - 1u) {
            g_bar = 0u;
            g_done = 0u;
            __threadfence();
        }
    }
}

extern "C" void kernel_launch(void* const* d_in, const int* in_sizes, int n_in,
                              void* d_out, int out_size)
{
    gru_tc<<<NCTA, NT>>>(
        (const float*)d_in[0], (const float*)d_in[1], (const float*)d_in[2],
        (const float*)d_in[3], (const float*)d_in[4], (const float*)d_in[5],
        (const float*)d_in[6], (const float*)d_in[7], (const float*)d_in[8],
        (const float*)d_in[9], (const float*)d_in[10], (float*)d_out);
}

// round 7
// speedup vs baseline: 5.0333x; 1.3877x over previous
#include <cuda_runtime.h>
#include <cuda_bf16.h>

#define B_   64
#define T_   512
#define DIN  256
#define H_   1024
#define DOUT 256
#define NCTA 128
#define NT   256

constexpr int KT0 = 16;   // Wi0 k-groups
constexpr int KTH = 64;   // Wh0/Wi1/Wh1 k-groups
constexpr size_t FSZ0 = (size_t)64 * 3 * KT0 * 64;
constexpr size_t FSZH = (size_t)64 * 3 * KTH * 64;
constexpr size_t FB0 = 0, FB1 = FSZ0, FB2 = FSZ0 + FSZH, FB3 = FSZ0 + 2 * FSZH;

__device__ uint4 g_wA[FSZ0 + 3 * FSZH];          // fragment-direct weights (hi/lo)
__device__ float g_h0f[2][B_ * H_], g_h1f[2][B_ * H_];
__device__ uint4 g_h0x[2][KTH * B_ * 4];         // frag-ordered h0 [kg][b][qq]
__device__ uint4 g_h1x[2][KTH * B_ * 4];
__device__ uint4 g_xx[(size_t)T_ * KT0 * B_ * 4];// frag-ordered x  [t][kg][b][qq]
__device__ float g_pL0[NCTA * 4096];             // partials [cta][qty4][j16][b64]
__device__ float g_pL1[NCTA * 4096];
__device__ volatile unsigned g_fL0[NCTA], g_fL1[NCTA];
__device__ unsigned g_bar, g_done;

__device__ __forceinline__ unsigned short bfbits(float v) {
    __nv_bfloat16 b = __float2bfloat16_rn(v);
    return *reinterpret_cast<unsigned short*>(&b);
}
__device__ __forceinline__ float bf2f(unsigned short u) {
    __nv_bfloat16 b = *reinterpret_cast<__nv_bfloat16*>(&u);
    return __bfloat162float(b);
}
__device__ __forceinline__ unsigned pk(float a, float b) {
    return (unsigned)bfbits(a) | ((unsigned)bfbits(b) << 16);
}
__device__ __forceinline__ float resid(float w) { return w - bf2f(bfbits(w)); }
__device__ __forceinline__ float sigf(float x) {
    return __fdividef(1.0f, 1.0f + __expf(-x));
}
__device__ __forceinline__ float tanh_(float x) {
    return __fdividef(2.0f, 1.0f + __expf(-2.0f * x)) - 1.0f;
}

__device__ __forceinline__ void mma16816(float (&d)[4], const uint4 a,
                                         unsigned b0, unsigned b1) {
    asm volatile(
        "mma.sync.aligned.m16n8k16.row.col.f32.bf16.bf16.f32 "
        "{%0,%1,%2,%3},{%4,%5,%6,%7},{%8,%9},{%0,%1,%2,%3};"
        : "+f"(d[0]), "+f"(d[1]), "+f"(d[2]), "+f"(d[3])
        : "r"(a.x), "r"(a.y), "r"(a.z), "r"(a.w), "r"(b0), "r"(b1));
}

__device__ __forceinline__ void grid_sync(unsigned gen) {
    __syncthreads();
    if (threadIdx.x == 0) {
        __threadfence();
        atomicAdd(&g_bar, 1u);
        while (*((volatile unsigned*)&g_bar) < gen * NCTA) { }
        __threadfence();
    }
    __syncthreads();
}

// One GEMM slice: 3 gates x 4 n8 (32 batch) x CNT k-groups, merged split-bf16
// chains (A_h*B_h + A_h*B_l + A_l*B_h into one fp32 accumulator).
template<int KT, int CNT>
__device__ __forceinline__ void mainloop(
    const uint4* __restrict__ fA,   // + jt*3*KT*64 + lane
    const uint4* __restrict__ bx,   // + nsub*128 + (lane>>2)*4 + (lane&3)
    int kgs,
    float (&aR)[4][4], float (&aZ)[4][4], float (&aN)[4][4])
{
    const uint4* a0 = fA + (size_t)kgs * 64;
    const uint4* bp = bx + (size_t)kgs * 256;
#pragma unroll 2
    for (int k = 0; k < CNT; ++k) {
        uint4 Ah0 = a0[0],           Al0 = a0[32];
        uint4 Ah1 = a0[KT * 64],     Al1 = a0[KT * 64 + 32];
        uint4 Ah2 = a0[2 * KT * 64], Al2 = a0[2 * KT * 64 + 32];
        uint4 v[4];
#pragma unroll
        for (int i = 0; i < 4; ++i) v[i] = bp[i * 32];
#pragma unroll
        for (int i = 0; i < 4; ++i) {
            mma16816(aR[i], Ah0, v[i].x, v[i].y);
            mma16816(aZ[i], Ah1, v[i].x, v[i].y);
            mma16816(aN[i], Ah2, v[i].x, v[i].y);
            mma16816(aR[i], Ah0, v[i].z, v[i].w);
            mma16816(aZ[i], Ah1, v[i].z, v[i].w);
            mma16816(aN[i], Ah2, v[i].z, v[i].w);
            mma16816(aR[i], Al0, v[i].x, v[i].y);
            mma16816(aZ[i], Al1, v[i].x, v[i].y);
            mma16816(aN[i], Al2, v[i].x, v[i].y);
        }
        a0 += 64; bp += 256;
    }
}

// ksub-reduce via SMEM + publish CTA partial [qty][j16][b64] to global.
#define REDUCE_PUBLISH(AR, AZ, ANI, ANH, POUT)                                 \
    do {                                                                       \
        if (ksub) {                                                           \
            float* dst = rbuf + (((ksub - 1) * 2 + nsub) * 64) * 32 + lane;   \
            _Pragma("unroll")                                                 \
            for (int i = 0; i < 16; ++i) {                                    \
                dst[(0 * 16 + i) * 32] = AR[i >> 2][i & 3];                   \
                dst[(1 * 16 + i) * 32] = AZ[i >> 2][i & 3];                   \
                dst[(2 * 16 + i) * 32] = ANI[i >> 2][i & 3];                  \
                dst[(3 * 16 + i) * 32] = ANH[i >> 2][i & 3];                  \
            }                                                                 \
        }                                                                     \
        __syncthreads();                                                      \
        if (ksub == 0) {                                                      \
            _Pragma("unroll")                                                 \
            for (int q = 0; q < 4; ++q) {                                     \
                _Pragma("unroll")                                             \
                for (int i = 0; i < 16; ++i) {                                \
                    float v = (q == 0 ? AR[i >> 2][i & 3]                     \
                             : q == 1 ? AZ[i >> 2][i & 3]                     \
                             : q == 2 ? ANI[i >> 2][i & 3]                    \
                                      : ANH[i >> 2][i & 3]);                  \
                    _Pragma("unroll")                                         \
                    for (int w = 0; w < 3; ++w)                               \
                        v += rbuf[((w * 2 + nsub) * 64 + q * 16 + i) * 32 + lane]; \
                    int jl = (lane >> 2) + 8 * ((i & 3) >> 1);                \
                    int b  = nsub * 32 + (i >> 2) * 8 + 2 * (lane & 3) + (i & 1); \
                    (POUT)[q * 1024 + jl * 64 + b] = v;                       \
                }                                                             \
            }                                                                 \
        }                                                                     \
        __syncthreads();                                                      \
    } while (0)

// Gate pass: this CTA gates local j rows [8*ks, 8*ks+8) for all 64 b.
__device__ __forceinline__ void gatepass(
    const float* __restrict__ pOwn, const float* __restrict__ pPar,
    const float* bsv,
    const float* __restrict__ hpf, float* __restrict__ hnf,
    uint4* __restrict__ hx,
    int jt, int ks, int tid)
{
    const int b = tid & 63, jl2 = tid >> 6;
#pragma unroll
    for (int jj = 0; jj < 2; ++jj) {
        int jl = 8 * ks + jl2 * 2 + jj;
        int j  = jt * 16 + jl;
        int o  = jl * 64 + b;
        float r  = pOwn[o]        + pPar[o];
        float z  = pOwn[1024 + o] + pPar[1024 + o];
        float ni = pOwn[2048 + o] + pPar[2048 + o];
        float nh = pOwn[3072 + o] + pPar[3072 + o];
        r = sigf(r + bsv[jj * 4 + 0]);
        z = sigf(z + bsv[jj * 4 + 1]);
        float n = tanh_(ni + bsv[jj * 4 + 2] + r * (nh + bsv[jj * 4 + 3]));
        float hp = hpf[b * H_ + j];
        float h  = n + z * (hp - n);
        hnf[b * H_ + j] = h;
        unsigned short uh = bfbits(h);
        unsigned short ul = bfbits(h - bf2f(uh));
        int kg = j >> 4, pw = (j & 15) >> 1, qq = pw & 3, sl = pw >> 2;
        char* base = (char*)(hx + (size_t)(kg * 64 + b) * 4 + qq);
        *(unsigned short*)(base + sl * 4 + (j & 1) * 2)     = uh;
        *(unsigned short*)(base + 8 + sl * 4 + (j & 1) * 2) = ul;
    }
}

__global__ void __launch_bounds__(NT, 1) gru_tc2(
    const float* __restrict__ x,
    const float* __restrict__ Wi0, const float* __restrict__ Wh0,
    const float* __restrict__ bi0, const float* __restrict__ bh0,
    const float* __restrict__ Wi1, const float* __restrict__ Wh1,
    const float* __restrict__ bi1, const float* __restrict__ bh1,
    const float* __restrict__ Wo,  const float* __restrict__ bo,
    float* __restrict__ out)
{
    __shared__ float rbuf[3 * 2 * 64 * 32];   // 48 KB ksub-reduce buffer

    const int tid  = threadIdx.x, lane = tid & 31, warp = tid >> 5;
    const int cta  = blockIdx.x;
    const int jt   = cta >> 1;       // j-tile (16 rows)
    const int ks   = cta & 1;        // k-half
    const int nsub = warp & 1;       // batch half (32)
    const int ksub = warp >> 1;      // k-quarter of the half

    // ---- prep: x -> fragment-ordered split-bf16 ----
    {
        unsigned* xw = (unsigned*)g_xx;
        const int XW = T_ * KT0 * B_ * 16;   // 8.4M u32 words
        for (int w = cta * NT + tid; w < XW; w += NCTA * NT) {
            int wi = w & 3, qq = (w >> 2) & 3, b = (w >> 4) & 63;
            int kg = (w >> 10) & 15, t = w >> 14;
            int pw = (wi & 1) ? qq + 4 : qq;
            int k  = kg * 16 + pw * 2;
            float v0 = x[((size_t)b * T_ + t) * DIN + k];
            float v1 = x[((size_t)b * T_ + t) * DIN + k + 1];
            xw[w] = (wi < 2) ? pk(v0, v1) : pk(resid(v0), resid(v1));
        }
    }
    // ---- zero initial state (buffer 1 is read first) ----
    {
        unsigned* z0 = (unsigned*)g_h0x[1];
        unsigned* z1 = (unsigned*)g_h1x[1];
        for (int i = cta * NT + tid; i < KTH * B_ * 16; i += NCTA * NT) {
            z0[i] = 0u; z1[i] = 0u;
        }
        for (int i = cta * NT + tid; i < B_ * H_; i += NCTA * NT) {
            g_h0f[1][i] = 0.f; g_h1f[1][i] = 0.f;
        }
    }
    // ---- weights -> fragment-direct split-bf16 table (verified R5/R6) ----
    {
        const float* Wp[4] = { Wi0, Wh0, Wi1, Wh1 };
        const int    Kp[4] = { DIN, H_, H_, H_ };
        const size_t Fp[4] = { FB0, FB1, FB2, FB3 };
        for (int p = 0; p < 4; ++p) {
            const int K = Kp[p], KT = K / 16;
            const float* W = Wp[p];
            const int total = 64 * 3 * KT * 32;
            for (int i = cta * NT + tid; i < total; i += NCTA * NT) {
                int l = i & 31, item = i >> 5;
                int kg = item % KT, g = (item / KT) % 3, jtt = item / (KT * 3);
                int m = l >> 2, kb = 2 * (l & 3);
                const float* r0 = W + (size_t)(g * H_ + jtt * 16 + m) * K + kg * 16 + kb;
                const float* r1 = r0 + 8 * (size_t)K;
                float w00 = r0[0], w01 = r0[1], w02 = r0[8], w03 = r0[9];
                float w10 = r1[0], w11 = r1[1], w12 = r1[8], w13 = r1[9];
                uint4 hv, lv;
                hv.x = pk(w00, w01); hv.y = pk(w10, w11);
                hv.z = pk(w02, w03); hv.w = pk(w12, w13);
                lv.x = pk(resid(w00), resid(w01)); lv.y = pk(resid(w10), resid(w11));
                lv.z = pk(resid(w02), resid(w03)); lv.w = pk(resid(w12), resid(w13));
                size_t base = Fp[p] + ((size_t)(jtt * 3 + g) * KT + kg) * 64;
                g_wA[base + l] = hv;
                g_wA[base + 32 + l] = lv;
            }
        }
    }
    // ---- per-thread gate-pass biases ----
    float bs0v[8], bs1v[8];
    {
        const int jl2 = tid >> 6;
#pragma unroll
        for (int jj = 0; jj < 2; ++jj) {
            int j = jt * 16 + 8 * ks + jl2 * 2 + jj;
            bs0v[jj * 4 + 0] = bi0[j] + bh0[j];
            bs0v[jj * 4 + 1] = bi0[H_ + j] + bh0[H_ + j];
            bs0v[jj * 4 + 2] = bi0[2 * H_ + j];
            bs0v[jj * 4 + 3] = bh0[2 * H_ + j];
            bs1v[jj * 4 + 0] = bi1[j] + bh1[j];
            bs1v[jj * 4 + 1] = bi1[H_ + j] + bh1[H_ + j];
            bs1v[jj * 4 + 2] = bi1[2 * H_ + j];
            bs1v[jj * 4 + 3] = bh1[2 * H_ + j];
        }
    }

    const uint4* fWi0 = g_wA + FB0 + (size_t)jt * 3 * KT0 * 64 + lane;
    const uint4* fWh0 = g_wA + FB1 + (size_t)jt * 3 * KTH * 64 + lane;
    const uint4* fWi1 = g_wA + FB2 + (size_t)jt * 3 * KTH * 64 + lane;
    const uint4* fWh1 = g_wA + FB3 + (size_t)jt * 3 * KTH * 64 + lane;
    const unsigned boff = nsub * 128 + (lane >> 2) * 4 + (lane & 3);
    const int kgs0 = ks * 8  + ksub * 2;   // Wi0 (KT=16): 2 kg per warp
    const int kgsH = ks * 32 + ksub * 8;   // KT=64 GEMMs: 8 kg per warp

    float* pOwn0 = g_pL0 + cta * 4096;
    float* pOwn1 = g_pL1 + cta * 4096;
    const float* pPar0 = g_pL0 + (cta ^ 1) * 4096;
    const float* pPar1 = g_pL1 + (cta ^ 1) * 4096;

    unsigned gen = 0;
    grid_sync(++gen);   // prep visible

    for (int p = 0; p <= T_; ++p) {
        // ---- layer0(t=p) partial: Wi0 x x(p) + Wh0 x h0(p-1) ----
        if (p < T_) {
            float aR[4][4] = {}, aZ[4][4] = {}, aNi[4][4] = {}, aNh[4][4] = {};
            mainloop<KT0, 2>(fWi0, g_xx + (size_t)p * 4096 + boff, kgs0, aR, aZ, aNi);
            mainloop<KTH, 8>(fWh0, g_h0x[(p + 1) & 1] + boff, kgsH, aR, aZ, aNh);
            REDUCE_PUBLISH(aR, aZ, aNi, aNh, pOwn0);
        }
        __syncthreads();
        if (tid == 0 && p < T_) { __threadfence(); g_fL0[cta] = p + 1; }
        // ---- layer1(t=p-1) partial: Wi1 x h0(p-1) + Wh1 x h1(p-2) ----
        if (p > 0) {
            float aR[4][4] = {}, aZ[4][4] = {}, aNi[4][4] = {}, aNh[4][4] = {};
            mainloop<KTH, 8>(fWi1, g_h0x[(p + 1) & 1] + boff, kgsH, aR, aZ, aNi);
            mainloop<KTH, 8>(fWh1, g_h1x[p & 1] + boff, kgsH, aR, aZ, aNh);
            REDUCE_PUBLISH(aR, aZ, aNi, aNh, pOwn1);
        }
        __syncthreads();
        if (tid == 0) {
            if (p > 0) { __threadfence(); g_fL1[cta] = p; }
            if (p < T_) while (g_fL0[cta ^ 1] < (unsigned)(p + 1)) { }
            if (p > 0)  while (g_fL1[cta ^ 1] < (unsigned)p) { }
            __threadfence();
        }
        __syncthreads();
        // ---- gate passes ----
        if (p < T_)
            gatepass(pOwn0, pPar0, bs0v, g_h0f[(p + 1) & 1], g_h0f[p & 1],
                     g_h0x[p & 1], jt, ks, tid);
        if (p > 0)
            gatepass(pOwn1, pPar1, bs1v, g_h1f[p & 1], g_h1f[(p + 1) & 1],
                     g_h1x[(p + 1) & 1], jt, ks, tid);
        grid_sync(++gen);
    }

    // ---- output projection: h1(511) is fp32 in g_h1f[1] ----
    if (tid < 128) {
        const int o = cta * 2 + (tid >> 6);
        const int b = tid & 63;
        const float* w  = Wo + (size_t)o * H_;
        const float* hv = g_h1f[1] + (size_t)b * H_;
        float acc = 0.f;
#pragma unroll 4
        for (int k = 0; k < H_; k += 4) {
            float4 wv = *reinterpret_cast<const float4*>(w + k);
            float4 h4 = *reinterpret_cast<const float4*>(hv + k);
            acc += wv.x * h4.x + wv.y * h4.y + wv.z * h4.z + wv.w * h4.w;
        }
        out[(size_t)b * DOUT + o] = acc + bo[o];
    }

    // ---- reset persistent counters/flags for the next replay ----
    __syncthreads();
    if (tid == 0) {
        unsigned old = atomicAdd(&g_done, 1u);
        if (old == NCTA - 1u) {
            for (int i = 0; i < NCTA; ++i) { g_fL0[i] = 0u; g_fL1[i] = 0u; }
            g_bar = 0u;
            g_done = 0u;
            __threadfence();
        }
    }
}

extern "C" void kernel_launch(void* const* d_in, const int* in_sizes, int n_in,
                              void* d_out, int out_size)
{
    gru_tc2<<<NCTA, NT>>>(
        (const float*)d_in[0], (const float*)d_in[1], (const float*)d_in[2],
        (const float*)d_in[3], (const float*)d_in[4], (const float*)d_in[5],
        (const float*)d_in[6], (const float*)d_in[7], (const float*)d_in[8],
        (const float*)d_in[9], (const float*)d_in[10], (float*)d_out);
}

// round 8
// speedup vs baseline: 5.1375x; 1.0207x over previous
#include <cuda_runtime.h>
#include <cuda_bf16.h>

#define B_   64
#define T_   512
#define DIN  256
#define H_   1024
#define DOUT 256
#define NCTA 128
#define NT   256

constexpr int KT0 = 16;   // Wi0 k-groups
constexpr int KTH = 64;   // Wh0/Wi1/Wh1 k-groups
constexpr int PD  = 4;    // cp.async pipeline depth (stages)
constexpr int SLOT = 10 * 512;              // bytes per stage per warp
constexpr int WREG = PD * SLOT;             // 20480 B per warp
constexpr int DYNSM = 8 * WREG;             // 163840 B

constexpr size_t FSZ0 = (size_t)64 * 3 * KT0 * 64;
constexpr size_t FSZH = (size_t)64 * 3 * KTH * 64;
constexpr size_t FB0 = 0, FB1 = FSZ0, FB2 = FSZ0 + FSZH, FB3 = FSZ0 + 2 * FSZH;

__device__ uint4 g_wA[FSZ0 + 3 * FSZH];          // fragment-direct weights (hi/lo)
__device__ float g_h0f[2][B_ * H_], g_h1f[2][B_ * H_];
__device__ uint4 g_h0x[2][KTH * B_ * 4];         // frag-ordered h0 [kg][b][qq]
__device__ uint4 g_h1x[2][KTH * B_ * 4];
__device__ uint4 g_xx[(size_t)T_ * KT0 * B_ * 4];// frag-ordered x  [t][kg][b][qq]
__device__ float g_pL0[NCTA * 4096];             // partials [cta][qty4][j16][b64]
__device__ float g_pL1[NCTA * 4096];
__device__ volatile unsigned g_fL0[NCTA], g_fL1[NCTA];
__device__ unsigned g_bar, g_done;

__device__ __forceinline__ unsigned short bfbits(float v) {
    __nv_bfloat16 b = __float2bfloat16_rn(v);
    return *reinterpret_cast<unsigned short*>(&b);
}
__device__ __forceinline__ float bf2f(unsigned short u) {
    __nv_bfloat16 b = *reinterpret_cast<__nv_bfloat16*>(&u);
    return __bfloat162float(b);
}
__device__ __forceinline__ unsigned pk(float a, float b) {
    return (unsigned)bfbits(a) | ((unsigned)bfbits(b) << 16);
}
__device__ __forceinline__ float resid(float w) { return w - bf2f(bfbits(w)); }
__device__ __forceinline__ float sigf(float x) {
    return __fdividef(1.0f, 1.0f + __expf(-x));
}
__device__ __forceinline__ float tanh_(float x) {
    return __fdividef(2.0f, 1.0f + __expf(-2.0f * x)) - 1.0f;
}

__device__ __forceinline__ void mma16816(float (&d)[4], const uint4 a,
                                         unsigned b0, unsigned b1) {
    asm volatile(
        "mma.sync.aligned.m16n8k16.row.col.f32.bf16.bf16.f32 "
        "{%0,%1,%2,%3},{%4,%5,%6,%7},{%8,%9},{%0,%1,%2,%3};"
        : "+f"(d[0]), "+f"(d[1]), "+f"(d[2]), "+f"(d[3])
        : "r"(a.x), "r"(a.y), "r"(a.z), "r"(a.w), "r"(b0), "r"(b1));
}

__device__ __forceinline__ void cp16(unsigned sdst, const void* gsrc) {
    asm volatile("cp.async.cg.shared.global [%0], [%1], 16;"
                 :: "r"(sdst), "l"(gsrc));
}
__device__ __forceinline__ void cp_commit() {
    asm volatile("cp.async.commit_group;");
}
template<int N>
__device__ __forceinline__ void cp_wait() {
    asm volatile("cp.async.wait_group %0;" :: "n"(N));
}
__device__ __forceinline__ uint4 lds128(unsigned a) {
    uint4 r;
    asm volatile("ld.shared.v4.u32 {%0,%1,%2,%3}, [%4];"
                 : "=r"(r.x), "=r"(r.y), "=r"(r.z), "=r"(r.w) : "r"(a));
    return r;
}

__device__ __forceinline__ void grid_sync(unsigned gen) {
    __syncthreads();
    if (threadIdx.x == 0) {
        __threadfence();
        atomicAdd(&g_bar, 1u);
        while (*((volatile unsigned*)&g_bar) < gen * NCTA) { }
        __threadfence();
    }
    __syncthreads();
}

// Pipelined GEMM slice: per-warp cp.async ring (depth PD) feeding the merged
// split-bf16 MMA block (3 gates x 4 n8 x fp32 accum).
template<int KT, int CNT>
__device__ __forceinline__ void mainloop_pipe(
    const uint4* __restrict__ fA,   // + jt*3*KT*64 + lane
    const uint4* __restrict__ bx,   // + nsub*128 + (lane>>2)*4 + (lane&3)
    int kgs, unsigned sbase,        // smem base for this warp (+lane*16)
    float (&aR)[4][4], float (&aZ)[4][4], float (&aN)[4][4])
{
    const uint4* a0 = fA + (size_t)kgs * 64;
    const uint4* bp = bx + (size_t)kgs * 256;

    auto issue = [&](int idx) {
        unsigned s = sbase + (unsigned)((idx & (PD - 1)) * SLOT);
        const uint4* aa = a0 + (size_t)idx * 64;
        const uint4* bb = bp + (size_t)idx * 256;
        cp16(s + 0 * 512, aa);
        cp16(s + 1 * 512, aa + 32);
        cp16(s + 2 * 512, aa + KT * 64);
        cp16(s + 3 * 512, aa + KT * 64 + 32);
        cp16(s + 4 * 512, aa + 2 * KT * 64);
        cp16(s + 5 * 512, aa + 2 * KT * 64 + 32);
        cp16(s + 6 * 512, bb);
        cp16(s + 7 * 512, bb + 32);
        cp16(s + 8 * 512, bb + 64);
        cp16(s + 9 * 512, bb + 96);
        cp_commit();
    };

#pragma unroll
    for (int i = 0; i < (CNT < PD ? CNT : PD); ++i) issue(i);

#pragma unroll
    for (int k = 0; k < CNT; ++k) {
        const int rem = CNT - 1 - k;      // groups that may stay pending
        if (rem >= 3) cp_wait<3>();
        else if (rem == 2) cp_wait<2>();
        else if (rem == 1) cp_wait<1>();
        else cp_wait<0>();

        unsigned s = sbase + (unsigned)((k & (PD - 1)) * SLOT);
        uint4 Ah0 = lds128(s + 0 * 512);
        uint4 Al0 = lds128(s + 1 * 512);
        uint4 Ah1 = lds128(s + 2 * 512);
        uint4 Al1 = lds128(s + 3 * 512);
        uint4 Ah2 = lds128(s + 4 * 512);
        uint4 Al2 = lds128(s + 5 * 512);
        uint4 v[4];
#pragma unroll
        for (int i = 0; i < 4; ++i) v[i] = lds128(s + (6 + i) * 512);

        if (k + PD < CNT) issue(k + PD);

#pragma unroll
        for (int i = 0; i < 4; ++i) {
            mma16816(aR[i], Ah0, v[i].x, v[i].y);
            mma16816(aZ[i], Ah1, v[i].x, v[i].y);
            mma16816(aN[i], Ah2, v[i].x, v[i].y);
            mma16816(aR[i], Ah0, v[i].z, v[i].w);
            mma16816(aZ[i], Ah1, v[i].z, v[i].w);
            mma16816(aN[i], Ah2, v[i].z, v[i].w);
            mma16816(aR[i], Al0, v[i].x, v[i].y);
            mma16816(aZ[i], Al1, v[i].x, v[i].y);
            mma16816(aN[i], Al2, v[i].x, v[i].y);
        }
    }
}

// ksub-reduce via SMEM + publish CTA partial [qty][j16][b64] to global.
#define REDUCE_PUBLISH(AR, AZ, ANI, ANH, POUT)                                 \
    do {                                                                       \
        if (ksub) {                                                           \
            float* dst = rbuf + (((ksub - 1) * 2 + nsub) * 64) * 32 + lane;   \
            _Pragma("unroll")                                                 \
            for (int i = 0; i < 16; ++i) {                                    \
                dst[(0 * 16 + i) * 32] = AR[i >> 2][i & 3];                   \
                dst[(1 * 16 + i) * 32] = AZ[i >> 2][i & 3];                   \
                dst[(2 * 16 + i) * 32] = ANI[i >> 2][i & 3];                  \
                dst[(3 * 16 + i) * 32] = ANH[i >> 2][i & 3];                  \
            }                                                                 \
        }                                                                     \
        __syncthreads();                                                      \
        if (ksub == 0) {                                                      \
            _Pragma("unroll")                                                 \
            for (int q = 0; q < 4; ++q) {                                     \
                _Pragma("unroll")                                             \
                for (int i = 0; i < 16; ++i) {                                \
                    float v = (q == 0 ? AR[i >> 2][i & 3]                     \
                             : q == 1 ? AZ[i >> 2][i & 3]                     \
                             : q == 2 ? ANI[i >> 2][i & 3]                    \
                                      : ANH[i >> 2][i & 3]);                  \
                    _Pragma("unroll")                                         \
                    for (int w = 0; w < 3; ++w)                               \
                        v += rbuf[((w * 2 + nsub) * 64 + q * 16 + i) * 32 + lane]; \
                    int jl = (lane >> 2) + 8 * ((i & 3) >> 1);                \
                    int b  = nsub * 32 + (i >> 2) * 8 + 2 * (lane & 3) + (i & 1); \
                    (POUT)[q * 1024 + jl * 64 + b] = v;                       \
                }                                                             \
            }                                                                 \
        }                                                                     \
        __syncthreads();                                                      \
    } while (0)

// Gate pass: this CTA gates local j rows [8*ks, 8*ks+8) for all 64 b.
__device__ __forceinline__ void gatepass(
    const float* __restrict__ pOwn, const float* __restrict__ pPar,
    const float* bsv,
    const float* __restrict__ hpf, float* __restrict__ hnf,
    uint4* __restrict__ hx,
    int jt, int ks, int tid)
{
    const int b = tid & 63, jl2 = tid >> 6;
#pragma unroll
    for (int jj = 0; jj < 2; ++jj) {
        int jl = 8 * ks + jl2 * 2 + jj;
        int j  = jt * 16 + jl;
        int o  = jl * 64 + b;
        float r  = pOwn[o]        + pPar[o];
        float z  = pOwn[1024 + o] + pPar[1024 + o];
        float ni = pOwn[2048 + o] + pPar[2048 + o];
        float nh = pOwn[3072 + o] + pPar[3072 + o];
        r = sigf(r + bsv[jj * 4 + 0]);
        z = sigf(z + bsv[jj * 4 + 1]);
        float n = tanh_(ni + bsv[jj * 4 + 2] + r * (nh + bsv[jj * 4 + 3]));
        float hp = hpf[b * H_ + j];
        float h  = n + z * (hp - n);
        hnf[b * H_ + j] = h;
        unsigned short uh = bfbits(h);
        unsigned short ul = bfbits(h - bf2f(uh));
        int kg = j >> 4, pw = (j & 15) >> 1, qq = pw & 3, sl = pw >> 2;
        char* base = (char*)(hx + (size_t)(kg * 64 + b) * 4 + qq);
        *(unsigned short*)(base + sl * 4 + (j & 1) * 2)     = uh;
        *(unsigned short*)(base + 8 + sl * 4 + (j & 1) * 2) = ul;
    }
}

__global__ void __launch_bounds__(NT, 1) gru_tc3(
    const float* __restrict__ x,
    const float* __restrict__ Wi0, const float* __restrict__ Wh0,
    const float* __restrict__ bi0, const float* __restrict__ bh0,
    const float* __restrict__ Wi1, const float* __restrict__ Wh1,
    const float* __restrict__ bi1, const float* __restrict__ bh1,
    const float* __restrict__ Wo,  const float* __restrict__ bo,
    float* __restrict__ out)
{
    __shared__ float rbuf[3 * 2 * 64 * 32];   // 48 KB ksub-reduce buffer
    extern __shared__ __align__(16) char dynsm[];

    const int tid  = threadIdx.x, lane = tid & 31, warp = tid >> 5;
    const int cta  = blockIdx.x;
    const int jt   = cta >> 1;       // j-tile (16 rows)
    const int ks   = cta & 1;        // k-half
    const int nsub = warp & 1;       // batch half (32)
    const int ksub = warp >> 1;      // k-quarter of the half

    const unsigned smb = (unsigned)__cvta_generic_to_shared(dynsm);
    const unsigned sbase = smb + (unsigned)warp * WREG + (unsigned)lane * 16;

    // ---- prep: x -> fragment-ordered split-bf16 ----
    {
        unsigned* xw = (unsigned*)g_xx;
        const int XW = T_ * KT0 * B_ * 16;
        for (int w = cta * NT + tid; w < XW; w += NCTA * NT) {
            int wi = w & 3, qq = (w >> 2) & 3, b = (w >> 4) & 63;
            int kg = (w >> 10) & 15, t = w >> 14;
            int pw = (wi & 1) ? qq + 4 : qq;
            int k  = kg * 16 + pw * 2;
            float v0 = x[((size_t)b * T_ + t) * DIN + k];
            float v1 = x[((size_t)b * T_ + t) * DIN + k + 1];
            xw[w] = (wi < 2) ? pk(v0, v1) : pk(resid(v0), resid(v1));
        }
    }
    // ---- zero initial state (buffer 1 is read first) ----
    {
        unsigned* z0 = (unsigned*)g_h0x[1];
        unsigned* z1 = (unsigned*)g_h1x[1];
        for (int i = cta * NT + tid; i < KTH * B_ * 16; i += NCTA * NT) {
            z0[i] = 0u; z1[i] = 0u;
        }
        for (int i = cta * NT + tid; i < B_ * H_; i += NCTA * NT) {
            g_h0f[1][i] = 0.f; g_h1f[1][i] = 0.f;
        }
    }
    // ---- weights -> fragment-direct split-bf16 table ----
    {
        const float* Wp[4] = { Wi0, Wh0, Wi1, Wh1 };
        const int    Kp[4] = { DIN, H_, H_, H_ };
        const size_t Fp[4] = { FB0, FB1, FB2, FB3 };
        for (int p = 0; p < 4; ++p) {
            const int K = Kp[p], KT = K / 16;
            const float* W = Wp[p];
            const int total = 64 * 3 * KT * 32;
            for (int i = cta * NT + tid; i < total; i += NCTA * NT) {
                int l = i & 31, item = i >> 5;
                int kg = item % KT, g = (item / KT) % 3, jtt = item / (KT * 3);
                int m = l >> 2, kb = 2 * (l & 3);
                const float* r0 = W + (size_t)(g * H_ + jtt * 16 + m) * K + kg * 16 + kb;
                const float* r1 = r0 + 8 * (size_t)K;
                float w00 = r0[0], w01 = r0[1], w02 = r0[8], w03 = r0[9];
                float w10 = r1[0], w11 = r1[1], w12 = r1[8], w13 = r1[9];
                uint4 hv, lv;
                hv.x = pk(w00, w01); hv.y = pk(w10, w11);
                hv.z = pk(w02, w03); hv.w = pk(w12, w13);
                lv.x = pk(resid(w00), resid(w01)); lv.y = pk(resid(w10), resid(w11));
                lv.z = pk(resid(w02), resid(w03)); lv.w = pk(resid(w12), resid(w13));
                size_t base = Fp[p] + ((size_t)(jtt * 3 + g) * KT + kg) * 64;
                g_wA[base + l] = hv;
                g_wA[base + 32 + l] = lv;
            }
        }
    }
    // ---- per-thread gate-pass biases ----
    float bs0v[8], bs1v[8];
    {
        const int jl2 = tid >> 6;
#pragma unroll
        for (int jj = 0; jj < 2; ++jj) {
            int j = jt * 16 + 8 * ks + jl2 * 2 + jj;
            bs0v[jj * 4 + 0] = bi0[j] + bh0[j];
            bs0v[jj * 4 + 1] = bi0[H_ + j] + bh0[H_ + j];
            bs0v[jj * 4 + 2] = bi0[2 * H_ + j];
            bs0v[jj * 4 + 3] = bh0[2 * H_ + j];
            bs1v[jj * 4 + 0] = bi1[j] + bh1[j];
            bs1v[jj * 4 + 1] = bi1[H_ + j] + bh1[H_ + j];
            bs1v[jj * 4 + 2] = bi1[2 * H_ + j];
            bs1v[jj * 4 + 3] = bh1[2 * H_ + j];
        }
    }

    const uint4* fWi0 = g_wA + FB0 + (size_t)jt * 3 * KT0 * 64 + lane;
    const uint4* fWh0 = g_wA + FB1 + (size_t)jt * 3 * KTH * 64 + lane;
    const uint4* fWi1 = g_wA + FB2 + (size_t)jt * 3 * KTH * 64 + lane;
    const uint4* fWh1 = g_wA + FB3 + (size_t)jt * 3 * KTH * 64 + lane;
    const unsigned boff = nsub * 128 + (lane >> 2) * 4 + (lane & 3);
    const int kgs0 = ks * 8  + ksub * 2;   // Wi0 (KT=16): 2 kg per warp
    const int kgsH = ks * 32 + ksub * 8;   // KT=64 GEMMs: 8 kg per warp

    float* pOwn0 = g_pL0 + cta * 4096;
    float* pOwn1 = g_pL1 + cta * 4096;
    const float* pPar0 = g_pL0 + (cta ^ 1) * 4096;
    const float* pPar1 = g_pL1 + (cta ^ 1) * 4096;

    unsigned gen = 0;
    grid_sync(++gen);   // prep visible

    for (int p = 0; p <= T_; ++p) {
        // ---- layer0(t=p) partial: Wi0 x x(p) + Wh0 x h0(p-1) ----
        if (p < T_) {
            float aR[4][4] = {}, aZ[4][4] = {}, aNi[4][4] = {}, aNh[4][4] = {};
            mainloop_pipe<KT0, 2>(fWi0, g_xx + (size_t)p * 4096 + boff, kgs0,
                                  sbase, aR, aZ, aNi);
            mainloop_pipe<KTH, 8>(fWh0, g_h0x[(p + 1) & 1] + boff, kgsH,
                                  sbase, aR, aZ, aNh);
            REDUCE_PUBLISH(aR, aZ, aNi, aNh, pOwn0);
        }
        __syncthreads();
        if (tid == 0 && p < T_) { __threadfence(); g_fL0[cta] = p + 1; }
        // ---- layer1(t=p-1) partial: Wi1 x h0(p-1) + Wh1 x h1(p-2) ----
        if (p > 0) {
            float aR[4][4] = {}, aZ[4][4] = {}, aNi[4][4] = {}, aNh[4][4] = {};
            mainloop_pipe<KTH, 8>(fWi1, g_h0x[(p + 1) & 1] + boff, kgsH,
                                  sbase, aR, aZ, aNi);
            mainloop_pipe<KTH, 8>(fWh1, g_h1x[p & 1] + boff, kgsH,
                                  sbase, aR, aZ, aNh);
            REDUCE_PUBLISH(aR, aZ, aNi, aNh, pOwn1);
        }
        __syncthreads();
        if (tid == 0) {
            if (p > 0) { __threadfence(); g_fL1[cta] = p; }
            if (p < T_) while (g_fL0[cta ^ 1] < (unsigned)(p + 1)) { }
            if (p > 0)  while (g_fL1[cta ^ 1] < (unsigned)p) { }
            __threadfence();
        }
        __syncthreads();
        // ---- gate passes ----
        if (p < T_)
            gatepass(pOwn0, pPar0, bs0v, g_h0f[(p + 1) & 1], g_h0f[p & 1],
                     g_h0x[p & 1], jt, ks, tid);
        if (p > 0)
            gatepass(pOwn1, pPar1, bs1v, g_h1f[p & 1], g_h1f[(p + 1) & 1],
                     g_h1x[(p + 1) & 1], jt, ks, tid);
        grid_sync(++gen);
    }

    // ---- output projection: h1(511) is fp32 in g_h1f[1] ----
    if (tid < 128) {
        const int o = cta * 2 + (tid >> 6);
        const int b = tid & 63;
        const float* w  = Wo + (size_t)o * H_;
        const float* hv = g_h1f[1] + (size_t)b * H_;
        float acc = 0.f;
#pragma unroll 4
        for (int k = 0; k < H_; k += 4) {
            float4 wv = *reinterpret_cast<const float4*>(w + k);
            float4 h4 = *reinterpret_cast<const float4*>(hv + k);
            acc += wv.x * h4.x + wv.y * h4.y + wv.z * h4.z + wv.w * h4.w;
        }
        out[(size_t)b * DOUT + o] = acc + bo[o];
    }

    // ---- reset persistent counters/flags for the next replay ----
    __syncthreads();
    if (tid == 0) {
        unsigned old = atomicAdd(&g_done, 1u);
        if (old == NCTA - 1u) {
            for (int i = 0; i < NCTA; ++i) { g_fL0[i] = 0u; g_fL1[i] = 0u; }
            g_bar = 0u;
            g_done = 0u;
            __threadfence();
        }
    }
}

extern "C" void kernel_launch(void* const* d_in, const int* in_sizes, int n_in,
                              void* d_out, int out_size)
{
    cudaFuncSetAttribute(gru_tc3, cudaFuncAttributeMaxDynamicSharedMemorySize,
                         DYNSM);
    gru_tc3<<<NCTA, NT, DYNSM>>>(
        (const float*)d_in[0], (const float*)d_in[1], (const float*)d_in[2],
        (const float*)d_in[3], (const float*)d_in[4], (const float*)d_in[5],
        (const float*)d_in[6], (const float*)d_in[7], (const float*)d_in[8],
        (const float*)d_in[9], (const float*)d_in[10], (float*)d_out);
}